// round 2
// baseline (speedup 1.0000x reference)
#include <cuda_runtime.h>
#include <cstdint>

// Problem constants
#define T_SEQ 128
#define BATCH 512
#define DIM   128
#define NQ    8
// 4 gates * 8 wires = 32 pre-activation channels per (t, b)
#define NCH   32

// Scratch: zpre[t*BATCH + b][ch] = x_t[b] @ Wx[:,ch]  (no bias)
__device__ float g_zpre[(size_t)T_SEQ * BATCH * NCH];

// ---------------------------------------------------------------------------
// Kernel A: zpre = X @ Wx  where X is (T*B, 128), Wx is (128, 32) assembled
// from the first 128 rows of Wf/Wi/Wu/Wo (each 136x8).
// Block: 128 threads, 128 rows. smem: ws[128][32] + xs (k-major, +1 pad).
// ---------------------------------------------------------------------------
__global__ void __launch_bounds__(128) qlstm_gemm(
    const float* __restrict__ x,
    const float* __restrict__ Wf, const float* __restrict__ Wi,
    const float* __restrict__ Wu, const float* __restrict__ Wo)
{
    __shared__ float ws[128][32];   // ws[k][gate*8+wire]
    __shared__ float xs[32][129];   // xs[k_in_chunk][row], padded: conflict-free
    const int tid  = threadIdx.x;
    const int row0 = blockIdx.x * 128;

    // Stage W (x-part only: rows 0..127 of each 136x8 gate weight)
    #pragma unroll 4
    for (int i = tid; i < 128 * 32; i += 128) {
        int k = i >> 5, j = i & 31;
        int g = j >> 3, w = j & 7;
        const float* Wg = (g == 0) ? Wf : (g == 1) ? Wi : (g == 2) ? Wu : Wo;
        ws[k][j] = Wg[k * 8 + w];
    }

    const int lane = tid & 31;
    const int c0   = (tid >> 5) * 8;   // warp-uniform column group (8 cols)

    float acc[4][8];
    #pragma unroll
    for (int r = 0; r < 4; r++)
        #pragma unroll
        for (int q = 0; q < 8; q++) acc[r][q] = 0.0f;

    // K staged in 4 chunks of 32 to stay under the static smem limit
    for (int kc = 0; kc < 4; ++kc) {
        __syncthreads();
        // coalesced load: each warp reads one row's 32 consecutive floats
        #pragma unroll 4
        for (int i = tid; i < 128 * 32; i += 128) {
            int r = i >> 5, kk = i & 31;
            xs[kk][r] = x[(size_t)(row0 + r) * DIM + kc * 32 + kk];
        }
        __syncthreads();

        #pragma unroll
        for (int k = 0; k < 32; ++k) {
            float xv0 = xs[k][lane];
            float xv1 = xs[k][lane + 32];
            float xv2 = xs[k][lane + 64];
            float xv3 = xs[k][lane + 96];
            const float* wk = &ws[kc * 32 + k][c0];
            #pragma unroll
            for (int q = 0; q < 8; ++q) {
                float wv = wk[q];
                acc[0][q] = fmaf(xv0, wv, acc[0][q]);
                acc[1][q] = fmaf(xv1, wv, acc[1][q]);
                acc[2][q] = fmaf(xv2, wv, acc[2][q]);
                acc[3][q] = fmaf(xv3, wv, acc[3][q]);
            }
        }
    }

    // Write out: thread owns rows lane+32*rr, cols c0..c0+7
    #pragma unroll
    for (int rr = 0; rr < 4; ++rr) {
        int r = row0 + lane + 32 * rr;
        float4* dst = reinterpret_cast<float4*>(g_zpre + (size_t)r * NCH + c0);
        dst[0] = make_float4(acc[rr][0], acc[rr][1], acc[rr][2], acc[rr][3]);
        dst[1] = make_float4(acc[rr][4], acc[rr][5], acc[rr][6], acc[rr][7]);
    }
}

// ---------------------------------------------------------------------------
// Kernel B: recurrent LSTM with the analytic quantum layer.
// One warp per batch row. Lane = gate*8 + wire.
// phi_j = zpre[t,b,j] + (b_g[w] + th_g[w]) + hx . Wh[:,j]
// c_j = cos(phi_j);  e_w = prod_{k<=w} c_k (w>=1),  e_0 = prod_{k=1..7} c_k
// f,i,o = sigmoid(e); g = tanh(e); standard LSTM cell update.
// ---------------------------------------------------------------------------
__global__ void __launch_bounds__(128) qlstm_recurrent(
    const float* __restrict__ Wf, const float* __restrict__ bf, const float* __restrict__ thf,
    const float* __restrict__ Wi, const float* __restrict__ bi, const float* __restrict__ thi,
    const float* __restrict__ Wu, const float* __restrict__ bu, const float* __restrict__ thu,
    const float* __restrict__ Wo, const float* __restrict__ bo, const float* __restrict__ tho,
    float* __restrict__ out)
{
    const int lane = threadIdx.x & 31;
    const int warp = threadIdx.x >> 5;
    const int row  = blockIdx.x * 4 + warp;       // 0..511
    const int gate = lane >> 3;
    const int wire = lane & 7;

    const float* Wg = (gate == 0) ? Wf : (gate == 1) ? Wi : (gate == 2) ? Wu : Wo;
    const float* bg = (gate == 0) ? bf : (gate == 1) ? bi : (gate == 2) ? bu : bo;
    const float* tg = (gate == 0) ? thf : (gate == 1) ? thi : (gate == 2) ? thu : tho;

    // recurrent weight column for this lane's output channel: Wh[k][wire], k=0..7
    float wcol[8];
    #pragma unroll
    for (int k = 0; k < 8; ++k) wcol[k] = Wg[(DIM + k) * NQ + wire];
    const float cbias = bg[wire] + tg[wire];
    const bool  isU   = (gate == 2);

    float h[8];
    #pragma unroll
    for (int k = 0; k < 8; ++k) h[k] = 0.0f;
    float cstate = 0.0f;

    const float* zp = g_zpre + (size_t)row * NCH + lane;
    float znext = zp[0];

    const unsigned FULL = 0xffffffffu;

    for (int t = 0; t < T_SEQ; ++t) {
        float z = znext + cbias;
        if (t + 1 < T_SEQ) znext = zp[(size_t)(t + 1) * BATCH * NCH]; // prefetch

        #pragma unroll
        for (int k = 0; k < 8; ++k) z = fmaf(h[k], wcol[k], z);

        float c = __cosf(z);

        // segmented (width 8) inclusive scan of products, with lane0 masked to 1:
        // p = prod_{k=1..wire} c_k
        float p = (wire == 0) ? 1.0f : c;
        #pragma unroll
        for (int d = 1; d < 8; d <<= 1) {
            float up = __shfl_up_sync(FULL, p, d, 8);
            if (wire >= d) p *= up;
        }
        float q7  = __shfl_sync(FULL, p, 7, 8);   // prod_{k=1..7} c_k
        float c0v = __shfl_sync(FULL, c, 0, 8);   // c_0
        float e   = (wire == 0) ? q7 : c0v * p;   // <Z_wire>

        // activation: sigmoid for f,i,o ; tanh for u (tanh(x)=2*sigmoid(2x)-1)
        float xin = isU ? (-2.0f * e) : (-e);
        float ex  = __expf(xin);
        float s   = __fdividef(1.0f, 1.0f + ex);
        float act = isU ? fmaf(2.0f, s, -1.0f) : s;

        // gather the four gate values for this wire
        float fv = __shfl_sync(FULL, act, wire);
        float iv = __shfl_sync(FULL, act, wire + 8);
        float gv = __shfl_sync(FULL, act, wire + 16);
        float ov = __shfl_sync(FULL, act, wire + 24);

        cstate   = fmaf(fv, cstate, iv * gv);
        float s2 = __fdividef(1.0f, 1.0f + __expf(-2.0f * cstate));
        float hw = ov * fmaf(2.0f, s2, -1.0f);

        if (lane < 8)
            out[((size_t)t * BATCH + row) * NQ + wire] = hw;

        // broadcast new hx (wire k lives on lane k) to all lanes
        #pragma unroll
        for (int k = 0; k < 8; ++k) h[k] = __shfl_sync(FULL, hw, k);
    }

    if (lane < 8) {
        const size_t outs_sz = (size_t)T_SEQ * BATCH * NQ;   // 524288
        out[outs_sz + (size_t)row * NQ + wire] = h[wire];                    // final hx
        out[outs_sz + (size_t)BATCH * NQ + (size_t)row * NQ + wire] = cstate; // final cx
    }
}

// ---------------------------------------------------------------------------
// Launch
// Inputs (metadata order): inputs, Wf, bf, th_f, Wi, bi, th_i,
//                          Wu, bu, th_u, Wo, bo, th_o
// Output: concat(outs [T,B,8], hx [B,8], cx [B,8]) as float32
// ---------------------------------------------------------------------------
extern "C" void kernel_launch(void* const* d_in, const int* in_sizes, int n_in,
                              void* d_out, int out_size)
{
    const float* x   = (const float*)d_in[0];
    const float* Wf  = (const float*)d_in[1];
    const float* bf  = (const float*)d_in[2];
    const float* thf = (const float*)d_in[3];
    const float* Wi  = (const float*)d_in[4];
    const float* bi  = (const float*)d_in[5];
    const float* thi = (const float*)d_in[6];
    const float* Wu  = (const float*)d_in[7];
    const float* bu  = (const float*)d_in[8];
    const float* thu = (const float*)d_in[9];
    const float* Wo  = (const float*)d_in[10];
    const float* bo  = (const float*)d_in[11];
    const float* tho = (const float*)d_in[12];
    float* out = (float*)d_out;

    // Kernel A: (T*B, 128) @ (128, 32) -> g_zpre
    qlstm_gemm<<<(T_SEQ * BATCH) / 128, 128>>>(x, Wf, Wi, Wu, Wo);

    // Kernel B: recurrence, one warp per batch row
    qlstm_recurrent<<<BATCH / 4, 128>>>(Wf, bf, thf, Wi, bi, thi,
                                        Wu, bu, thu, Wo, bo, tho, out);
}

// round 3
// speedup vs baseline: 1.1207x; 1.1207x over previous
#include <cuda_runtime.h>
#include <cstdint>

// Problem constants
#define T_SEQ 128
#define BATCH 512
#define DIM   128
#define NQ    8
#define NCH   32   // 4 gates * 8 wires

// Scratch: zpre[t*BATCH + b][ch] = x_t[b] @ Wx[:,ch], ch = gate*8+wire
__device__ float g_zpre[(size_t)T_SEQ * BATCH * NCH];

__device__ __forceinline__ float tanh_approx(float x) {
    float r;
    asm("tanh.approx.f32 %0, %1;" : "=f"(r) : "f"(x));
    return r;
}

// ---------------------------------------------------------------------------
// Kernel A: zpre = X @ Wx  (X: (T*B,128), Wx: (128,32) from x-rows of W*)
// ---------------------------------------------------------------------------
__global__ void __launch_bounds__(128) qlstm_gemm(
    const float* __restrict__ x,
    const float* __restrict__ Wf, const float* __restrict__ Wi,
    const float* __restrict__ Wu, const float* __restrict__ Wo)
{
    __shared__ float ws[128][32];   // ws[k][gate*8+wire]
    __shared__ float xs[32][129];   // padded, conflict-free
    const int tid  = threadIdx.x;
    const int row0 = blockIdx.x * 128;

    #pragma unroll 4
    for (int i = tid; i < 128 * 32; i += 128) {
        int k = i >> 5, j = i & 31;
        int g = j >> 3, w = j & 7;
        const float* Wg = (g == 0) ? Wf : (g == 1) ? Wi : (g == 2) ? Wu : Wo;
        ws[k][j] = Wg[k * 8 + w];
    }

    const int lane = tid & 31;
    const int c0   = (tid >> 5) * 8;

    float acc[4][8];
    #pragma unroll
    for (int r = 0; r < 4; r++)
        #pragma unroll
        for (int q = 0; q < 8; q++) acc[r][q] = 0.0f;

    for (int kc = 0; kc < 4; ++kc) {
        __syncthreads();
        #pragma unroll 4
        for (int i = tid; i < 128 * 32; i += 128) {
            int r = i >> 5, kk = i & 31;
            xs[kk][r] = x[(size_t)(row0 + r) * DIM + kc * 32 + kk];
        }
        __syncthreads();

        #pragma unroll
        for (int k = 0; k < 32; ++k) {
            float xv0 = xs[k][lane];
            float xv1 = xs[k][lane + 32];
            float xv2 = xs[k][lane + 64];
            float xv3 = xs[k][lane + 96];
            const float* wk = &ws[kc * 32 + k][c0];
            #pragma unroll
            for (int q = 0; q < 8; ++q) {
                float wv = wk[q];
                acc[0][q] = fmaf(xv0, wv, acc[0][q]);
                acc[1][q] = fmaf(xv1, wv, acc[1][q]);
                acc[2][q] = fmaf(xv2, wv, acc[2][q]);
                acc[3][q] = fmaf(xv3, wv, acc[3][q]);
            }
        }
    }

    #pragma unroll
    for (int rr = 0; rr < 4; ++rr) {
        int r = row0 + lane + 32 * rr;
        float4* dst = reinterpret_cast<float4*>(g_zpre + (size_t)r * NCH + c0);
        dst[0] = make_float4(acc[rr][0], acc[rr][1], acc[rr][2], acc[rr][3]);
        dst[1] = make_float4(acc[rr][4], acc[rr][5], acc[rr][6], acc[rr][7]);
    }
}

// ---------------------------------------------------------------------------
// Kernel B: recurrence. One warp per batch row; lane = gate*8 + wire.
// <Z_w> = prod_{k<=w} cos(phi_k) (w>=1), <Z_0> = prod_{k=1..7} cos(phi_k).
// Chain-minimized: allgather+Sklansky prefix, MUFU.TANH activations,
// branch-free body.
// ---------------------------------------------------------------------------
__global__ void __launch_bounds__(128) qlstm_recurrent(
    const float* __restrict__ Wf, const float* __restrict__ bf, const float* __restrict__ thf,
    const float* __restrict__ Wi, const float* __restrict__ bi, const float* __restrict__ thi,
    const float* __restrict__ Wu, const float* __restrict__ bu, const float* __restrict__ thu,
    const float* __restrict__ Wo, const float* __restrict__ bo, const float* __restrict__ tho,
    float* __restrict__ out)
{
    const int lane = threadIdx.x & 31;
    const int warp = threadIdx.x >> 5;
    const int row  = blockIdx.x * 4 + warp;       // 0..511
    const int gate = lane >> 3;
    const int wire = lane & 7;
    const int base = lane & 24;                    // gate*8: segment start

    const float* Wg = (gate == 0) ? Wf : (gate == 1) ? Wi : (gate == 2) ? Wu : Wo;
    const float* bg = (gate == 0) ? bf : (gate == 1) ? bi : (gate == 2) ? bu : bo;
    const float* tg = (gate == 0) ? thf : (gate == 1) ? thi : (gate == 2) ? thu : tho;

    float w0 = Wg[(DIM + 0) * NQ + wire];
    float w1 = Wg[(DIM + 1) * NQ + wire];
    float w2 = Wg[(DIM + 2) * NQ + wire];
    float w3 = Wg[(DIM + 3) * NQ + wire];
    float w4 = Wg[(DIM + 4) * NQ + wire];
    float w5 = Wg[(DIM + 5) * NQ + wire];
    float w6 = Wg[(DIM + 6) * NQ + wire];
    float w7 = Wg[(DIM + 7) * NQ + wire];

    const float cbias = bg[wire] + tg[wire];
    const bool  isU   = (gate == 2);
    const float aScl  = isU ? 1.0f : 0.5f;   // tanh arg scale
    const float aMul  = isU ? 1.0f : 0.5f;   // post scale
    const float aAdd  = isU ? 0.0f : 0.5f;   // post bias

    // hoisted mux predicates
    const bool b0 = (wire & 1) != 0;
    const bool b1 = (wire & 2) != 0;
    const bool b2 = (wire & 4) != 0;

    float h0=0,h1=0,h2=0,h3=0,h4=0,h5=0,h6=0,h7=0;
    float cstate = 0.0f;

    const float* zp = g_zpre + (size_t)row * NCH + lane;
    const size_t tstride = (size_t)BATCH * NCH;
    float znext = zp[0];

    const unsigned FULL = 0xffffffffu;

    #pragma unroll 2
    for (int t = 0; t < T_SEQ; ++t) {
        float zb = znext + cbias;                 // off-chain
        int tn = (t + 1 < T_SEQ) ? (t + 1) : (T_SEQ - 1);
        znext = zp[(size_t)tn * tstride];         // branch-free prefetch

        // z = zb + h . wcol  (mul + add tree, depth ~20 from h arrival)
        float m0 = h0*w0, m1 = h1*w1, m2 = h2*w2, m3 = h3*w3;
        float m4 = h4*w4, m5 = h5*w5, m6 = h6*w6, m7 = h7*w7;
        float a01 = m0+m1, a23 = m2+m3, a45 = m4+m5, a67 = m6+m7;
        float z = ((a01+a23) + (a45+a67)) + zb;

        float c = __cosf(z);

        // allgather the 8 cos values of this gate's segment (parallel shfls)
        float cc0 = __shfl_sync(FULL, c, base + 0);
        float cc1 = __shfl_sync(FULL, c, base + 1);
        float cc2 = __shfl_sync(FULL, c, base + 2);
        float cc3 = __shfl_sync(FULL, c, base + 3);
        float cc4 = __shfl_sync(FULL, c, base + 4);
        float cc5 = __shfl_sync(FULL, c, base + 5);
        float cc6 = __shfl_sync(FULL, c, base + 6);
        float cc7 = __shfl_sync(FULL, c, base + 7);

        // prefix products, depth 12
        float m01 = cc0*cc1, m23 = cc2*cc3, m45 = cc4*cc5, m67 = cc6*cc7;
        float m0123 = m01*m23, m4567 = m45*m67;
        float P1 = m01;
        float P2 = m01*cc2;
        float P3 = m0123;
        float P4 = m0123*cc4;
        float P5 = m0123*m45;
        float P6 = m0123*(m45*cc6);
        float P7 = m0123*m4567;
        float E0 = (cc1*m23)*m4567;              // prod c1..c7 (wire 0 case)

        // mux by wire bits, depth 12
        float t0 = b0 ? P1 : E0;
        float t1 = b0 ? P3 : P2;
        float t2 = b0 ? P5 : P4;
        float t3 = b0 ? P7 : P6;
        float u0 = b1 ? t1 : t0;
        float u1 = b1 ? t3 : t2;
        float e  = b2 ? u1 : u0;                 // <Z_wire>

        // activation: sigmoid via tanh for f,i,o; tanh for u. One MUFU.
        float act = fmaf(aMul, tanh_approx(e * aScl), aAdd);

        // gather the four gate values of this wire (parallel shfls)
        float fv = __shfl_sync(FULL, act, wire);
        float iv = __shfl_sync(FULL, act, wire + 8);
        float gv = __shfl_sync(FULL, act, wire + 16);
        float ov = __shfl_sync(FULL, act, wire + 24);

        cstate   = fmaf(fv, cstate, iv * gv);
        float hw = ov * tanh_approx(cstate);

        if (lane < 8)
            out[((size_t)t * BATCH + row) * NQ + wire] = hw;

        // broadcast new hx (wire k lives on lane k of gate-0 segment)
        h0 = __shfl_sync(FULL, hw, 0);
        h1 = __shfl_sync(FULL, hw, 1);
        h2 = __shfl_sync(FULL, hw, 2);
        h3 = __shfl_sync(FULL, hw, 3);
        h4 = __shfl_sync(FULL, hw, 4);
        h5 = __shfl_sync(FULL, hw, 5);
        h6 = __shfl_sync(FULL, hw, 6);
        h7 = __shfl_sync(FULL, hw, 7);
    }

    if (lane < 8) {
        const size_t outs_sz = (size_t)T_SEQ * BATCH * NQ;
        float hmy = (wire==0)?h0:(wire==1)?h1:(wire==2)?h2:(wire==3)?h3:
                    (wire==4)?h4:(wire==5)?h5:(wire==6)?h6:h7;
        out[outs_sz + (size_t)row * NQ + wire] = hmy;                          // final hx
        out[outs_sz + (size_t)BATCH * NQ + (size_t)row * NQ + wire] = cstate;  // final cx
    }
}

// ---------------------------------------------------------------------------
// Launch
// ---------------------------------------------------------------------------
extern "C" void kernel_launch(void* const* d_in, const int* in_sizes, int n_in,
                              void* d_out, int out_size)
{
    const float* x   = (const float*)d_in[0];
    const float* Wf  = (const float*)d_in[1];
    const float* bf  = (const float*)d_in[2];
    const float* thf = (const float*)d_in[3];
    const float* Wi  = (const float*)d_in[4];
    const float* bi  = (const float*)d_in[5];
    const float* thi = (const float*)d_in[6];
    const float* Wu  = (const float*)d_in[7];
    const float* bu  = (const float*)d_in[8];
    const float* thu = (const float*)d_in[9];
    const float* Wo  = (const float*)d_in[10];
    const float* bo  = (const float*)d_in[11];
    const float* tho = (const float*)d_in[12];
    float* out = (float*)d_out;

    qlstm_gemm<<<(T_SEQ * BATCH) / 128, 128>>>(x, Wf, Wi, Wu, Wo);
    qlstm_recurrent<<<BATCH / 4, 128>>>(Wf, bf, thf, Wi, bi, thi,
                                        Wu, bu, thu, Wo, bo, tho, out);
}

// round 4
// speedup vs baseline: 1.1251x; 1.0039x over previous
#include <cuda_runtime.h>
#include <cstdint>

#define T_SEQ 128
#define BATCH 512
#define DIM   128
#define NQ    8
#define NCH   32   // 4 gates * 8 wires

typedef unsigned long long u64;

// Scratch: zpre[t*BATCH + b][ch] = x_t[b] @ Wx[:,ch], ch = gate*8+wire
__device__ float g_zpre[(size_t)T_SEQ * BATCH * NCH];

__device__ __forceinline__ float tanh_approx(float x) {
    float r;
    asm("tanh.approx.f32 %0, %1;" : "=f"(r) : "f"(x));
    return r;
}
__device__ __forceinline__ void ffma2(u64& acc, u64 a, u64 b) {
    asm("fma.rn.f32x2 %0, %1, %2, %0;" : "+l"(acc) : "l"(a), "l"(b));
}
__device__ __forceinline__ u64 pack2(float lo, float hi) {
    u64 r; asm("mov.b64 %0, {%1, %2};" : "=l"(r) : "f"(lo), "f"(hi)); return r;
}

// ---------------------------------------------------------------------------
// Kernel A: zpre = X @ Wx  (X: (T*B,128), Wx: (128,32) from x-rows of W*)
// Packed f32x2 FMA: column pairs live in 64-bit regs; weights load straight
// from smem as 64-bit register pairs (LDS.128 quads, no repacking).
// ---------------------------------------------------------------------------
__global__ void __launch_bounds__(128) qlstm_gemm(
    const float* __restrict__ x,
    const float* __restrict__ Wf, const float* __restrict__ Wi,
    const float* __restrict__ Wu, const float* __restrict__ Wo)
{
    __shared__ __align__(16) float ws[128][32];   // ws[k][gate*8+wire]
    __shared__ float xs[32][129];                 // padded, conflict-free
    const int tid  = threadIdx.x;
    const int row0 = blockIdx.x * 128;

    #pragma unroll 4
    for (int i = tid; i < 128 * 32; i += 128) {
        int k = i >> 5, j = i & 31;
        int g = j >> 3, w = j & 7;
        const float* Wg = (g == 0) ? Wf : (g == 1) ? Wi : (g == 2) ? Wu : Wo;
        ws[k][j] = Wg[k * 8 + w];
    }

    const int lane = tid & 31;
    const int c0   = (tid >> 5) * 8;    // warp-uniform column group (8 cols)

    u64 acc[4][4];                      // [row-group][col-pair]
    #pragma unroll
    for (int r = 0; r < 4; r++)
        #pragma unroll
        for (int q = 0; q < 4; q++) acc[r][q] = 0ull;

    for (int kc = 0; kc < 4; ++kc) {
        __syncthreads();
        #pragma unroll 4
        for (int i = tid; i < 128 * 32; i += 128) {
            int r = i >> 5, kk = i & 31;
            xs[kk][r] = x[(size_t)(row0 + r) * DIM + kc * 32 + kk];
        }
        __syncthreads();

        #pragma unroll
        for (int k = 0; k < 32; ++k) {
            float xv0 = xs[k][lane      ];
            float xv1 = xs[k][lane + 32 ];
            float xv2 = xs[k][lane + 64 ];
            float xv3 = xs[k][lane + 96 ];
            u64 xx0 = pack2(xv0, xv0);
            u64 xx1 = pack2(xv1, xv1);
            u64 xx2 = pack2(xv2, xv2);
            u64 xx3 = pack2(xv3, xv3);
            const u64* wk = reinterpret_cast<const u64*>(&ws[kc * 32 + k][c0]);
            u64 w0 = wk[0], w1 = wk[1], w2 = wk[2], w3 = wk[3];
            ffma2(acc[0][0], xx0, w0); ffma2(acc[0][1], xx0, w1);
            ffma2(acc[0][2], xx0, w2); ffma2(acc[0][3], xx0, w3);
            ffma2(acc[1][0], xx1, w0); ffma2(acc[1][1], xx1, w1);
            ffma2(acc[1][2], xx1, w2); ffma2(acc[1][3], xx1, w3);
            ffma2(acc[2][0], xx2, w0); ffma2(acc[2][1], xx2, w1);
            ffma2(acc[2][2], xx2, w2); ffma2(acc[2][3], xx2, w3);
            ffma2(acc[3][0], xx3, w0); ffma2(acc[3][1], xx3, w1);
            ffma2(acc[3][2], xx3, w2); ffma2(acc[3][3], xx3, w3);
        }
    }

    #pragma unroll
    for (int rr = 0; rr < 4; ++rr) {
        int r = row0 + lane + 32 * rr;
        u64* dst = reinterpret_cast<u64*>(g_zpre + (size_t)r * NCH + c0);
        dst[0] = acc[rr][0]; dst[1] = acc[rr][1];
        dst[2] = acc[rr][2]; dst[3] = acc[rr][3];
    }
}

// ---------------------------------------------------------------------------
// Kernel B: recurrence. One warp per batch row; lane = gate*8 + wire.
// <Z_w> = prod_{k<=w} cos(phi_k) (w>=1), <Z_0> = prod_{k=1..7} cos(phi_k).
// Depth-2 z prefetch hides L2 latency behind two step-chains.
// ---------------------------------------------------------------------------
__global__ void __launch_bounds__(128) qlstm_recurrent(
    const float* __restrict__ Wf, const float* __restrict__ bf, const float* __restrict__ thf,
    const float* __restrict__ Wi, const float* __restrict__ bi, const float* __restrict__ thi,
    const float* __restrict__ Wu, const float* __restrict__ bu, const float* __restrict__ thu,
    const float* __restrict__ Wo, const float* __restrict__ bo, const float* __restrict__ tho,
    float* __restrict__ out)
{
    const int lane = threadIdx.x & 31;
    const int warp = threadIdx.x >> 5;
    const int row  = blockIdx.x * 4 + warp;       // 0..511
    const int gate = lane >> 3;
    const int wire = lane & 7;
    const int base = lane & 24;                    // gate*8

    const float* Wg = (gate == 0) ? Wf : (gate == 1) ? Wi : (gate == 2) ? Wu : Wo;
    const float* bg = (gate == 0) ? bf : (gate == 1) ? bi : (gate == 2) ? bu : bo;
    const float* tg = (gate == 0) ? thf : (gate == 1) ? thi : (gate == 2) ? thu : tho;

    float w0 = Wg[(DIM + 0) * NQ + wire];
    float w1 = Wg[(DIM + 1) * NQ + wire];
    float w2 = Wg[(DIM + 2) * NQ + wire];
    float w3 = Wg[(DIM + 3) * NQ + wire];
    float w4 = Wg[(DIM + 4) * NQ + wire];
    float w5 = Wg[(DIM + 5) * NQ + wire];
    float w6 = Wg[(DIM + 6) * NQ + wire];
    float w7 = Wg[(DIM + 7) * NQ + wire];

    const float cbias = bg[wire] + tg[wire];
    const bool  isU   = (gate == 2);
    const float aScl  = isU ? 1.0f : 0.5f;
    const float aMul  = isU ? 1.0f : 0.5f;
    const float aAdd  = isU ? 0.0f : 0.5f;

    const bool b0 = (wire & 1) != 0;
    const bool b1 = (wire & 2) != 0;
    const bool b2 = (wire & 4) != 0;

    float h0=0,h1=0,h2=0,h3=0,h4=0,h5=0,h6=0,h7=0;
    float cstate = 0.0f;

    const float* zp = g_zpre + (size_t)row * NCH + lane;
    const size_t tstride = (size_t)BATCH * NCH;

    // depth-2 rolling prefetch
    float zn0 = zp[0];
    float zn1 = zp[tstride];

    float* outw = out + (size_t)row * NQ + wire;

    const unsigned FULL = 0xffffffffu;

    #pragma unroll 2
    for (int t = 0; t < T_SEQ; ++t) {
        float zb = zn0 + cbias;
        zn0 = zn1;
        int t2 = (t + 2 < T_SEQ) ? (t + 2) : (T_SEQ - 1);
        zn1 = zp[(size_t)t2 * tstride];

        // z = zb + h . wcol  (mul + add tree)
        float m0 = h0*w0, m1 = h1*w1, m2 = h2*w2, m3 = h3*w3;
        float m4 = h4*w4, m5 = h5*w5, m6 = h6*w6, m7 = h7*w7;
        float a01 = m0+m1, a23 = m2+m3, a45 = m4+m5, a67 = m6+m7;
        float z = ((a01+a23) + (a45+a67)) + zb;

        float c = __cosf(z);

        // allgather segment cosines
        float cc0 = __shfl_sync(FULL, c, base + 0);
        float cc1 = __shfl_sync(FULL, c, base + 1);
        float cc2 = __shfl_sync(FULL, c, base + 2);
        float cc3 = __shfl_sync(FULL, c, base + 3);
        float cc4 = __shfl_sync(FULL, c, base + 4);
        float cc5 = __shfl_sync(FULL, c, base + 5);
        float cc6 = __shfl_sync(FULL, c, base + 6);
        float cc7 = __shfl_sync(FULL, c, base + 7);

        // prefix products
        float m01 = cc0*cc1, m23 = cc2*cc3, m45 = cc4*cc5, m67 = cc6*cc7;
        float m0123 = m01*m23, m4567 = m45*m67;
        float P1 = m01;
        float P2 = m01*cc2;
        float P3 = m0123;
        float P4 = m0123*cc4;
        float P5 = m0123*m45;
        float P6 = m0123*(m45*cc6);
        float P7 = m0123*m4567;
        float E0 = (cc1*m23)*m4567;          // prod c1..c7

        // mux by wire bits
        float t0v = b0 ? P1 : E0;
        float t1v = b0 ? P3 : P2;
        float t2v = b0 ? P5 : P4;
        float t3v = b0 ? P7 : P6;
        float u0 = b1 ? t1v : t0v;
        float u1 = b1 ? t3v : t2v;
        float e  = b2 ? u1 : u0;             // <Z_wire>

        // activation: sigmoid via tanh for f,i,o; tanh for u
        float act = fmaf(aMul, tanh_approx(e * aScl), aAdd);

        // gather the four gate values of this wire
        float fv = __shfl_sync(FULL, act, wire);
        float iv = __shfl_sync(FULL, act, wire + 8);
        float gv = __shfl_sync(FULL, act, wire + 16);
        float ov = __shfl_sync(FULL, act, wire + 24);

        cstate   = fmaf(fv, cstate, iv * gv);
        float hw = ov * tanh_approx(cstate);

        if (lane < 8)
            outw[(size_t)t * (BATCH * NQ)] = hw;

        // broadcast new hx
        h0 = __shfl_sync(FULL, hw, 0);
        h1 = __shfl_sync(FULL, hw, 1);
        h2 = __shfl_sync(FULL, hw, 2);
        h3 = __shfl_sync(FULL, hw, 3);
        h4 = __shfl_sync(FULL, hw, 4);
        h5 = __shfl_sync(FULL, hw, 5);
        h6 = __shfl_sync(FULL, hw, 6);
        h7 = __shfl_sync(FULL, hw, 7);
    }

    if (lane < 8) {
        const size_t outs_sz = (size_t)T_SEQ * BATCH * NQ;
        float hmy = (wire==0)?h0:(wire==1)?h1:(wire==2)?h2:(wire==3)?h3:
                    (wire==4)?h4:(wire==5)?h5:(wire==6)?h6:h7;
        out[outs_sz + (size_t)row * NQ + wire] = hmy;                          // final hx
        out[outs_sz + (size_t)BATCH * NQ + (size_t)row * NQ + wire] = cstate;  // final cx
    }
}

// ---------------------------------------------------------------------------
// Launch
// ---------------------------------------------------------------------------
extern "C" void kernel_launch(void* const* d_in, const int* in_sizes, int n_in,
                              void* d_out, int out_size)
{
    const float* x   = (const float*)d_in[0];
    const float* Wf  = (const float*)d_in[1];
    const float* bf  = (const float*)d_in[2];
    const float* thf = (const float*)d_in[3];
    const float* Wi  = (const float*)d_in[4];
    const float* bi  = (const float*)d_in[5];
    const float* thi = (const float*)d_in[6];
    const float* Wu  = (const float*)d_in[7];
    const float* bu  = (const float*)d_in[8];
    const float* thu = (const float*)d_in[9];
    const float* Wo  = (const float*)d_in[10];
    const float* bo  = (const float*)d_in[11];
    const float* tho = (const float*)d_in[12];
    float* out = (float*)d_out;

    qlstm_gemm<<<(T_SEQ * BATCH) / 128, 128>>>(x, Wf, Wi, Wu, Wo);
    qlstm_recurrent<<<BATCH / 4, 128>>>(Wf, bf, thf, Wi, bi, thi,
                                        Wu, bu, thu, Wo, bo, tho, out);
}